// round 4
// baseline (speedup 1.0000x reference)
#include <cuda_runtime.h>
#include <math.h>

// Problem shape (fixed): DEPTH=4, B=4096, H=E=1024, K=2048, N=4H=4096
#define BATCH 4096
#define HID   1024
#define KDIM  2048
#define NDIM  4096

// 64 MB scratch for pre-activation Z of one layer (device global: no allocs allowed)
__device__ float g_scratch[(size_t)BATCH * NDIM];

// ---------------------------------------------------------------------------
// SGEMM: Z[4096,4096] = [X | Hh] (4096x2048) @ W (2048x4096)
// 128x128 block tile, BK=16, 256 threads, 8x8 register microtile.
// A is virtually concatenated: k<1024 -> X, else Hh. BK=16 divides 1024 so a
// K-tile never straddles the boundary.
// ---------------------------------------------------------------------------
__global__ __launch_bounds__(256, 2) void gemm128_kernel(
    const float* __restrict__ X,    // [4096,1024] row-major (layer input)
    const float* __restrict__ Hh,   // [4096,1024] row-major (s_h for this layer)
    const float* __restrict__ W)    // [2048,4096] row-major
{
    __shared__ float As[16 * 132];  // [k][m], padded stride 132 to cut store conflicts
    __shared__ float Bs[16 * 128];  // [k][n]

    const int tid = threadIdx.x;
    const int bm = blockIdx.y * 128;
    const int bn = blockIdx.x * 128;

    const int tm = (tid >> 4) << 3;   // 0..120 step 8
    const int tn = (tid & 15) << 3;   // 0..120 step 8

    float acc[8][8] = {};

    // A loads: 2 x float4 per thread (rows tid/4 and tid/4+64, k = (tid%4)*4)
    const int a_row = tid >> 2;
    const int a_k   = (tid & 3) << 2;
    // B loads: 2 x float4 per thread (rows tid/32 and tid/32+8, col = (tid%32)*4)
    const int b_row = tid >> 5;
    const int b_col = (tid & 31) << 2;

    for (int kt = 0; kt < KDIM; kt += 16) {
        const float* Asrc = (kt < HID) ? (X + kt) : (Hh + (kt - HID));
        #pragma unroll
        for (int r = 0; r < 2; ++r) {
            const int row = a_row + r * 64;
            float4 v = *reinterpret_cast<const float4*>(
                Asrc + (size_t)(bm + row) * HID + a_k);
            As[(a_k + 0) * 132 + row] = v.x;
            As[(a_k + 1) * 132 + row] = v.y;
            As[(a_k + 2) * 132 + row] = v.z;
            As[(a_k + 3) * 132 + row] = v.w;
        }
        #pragma unroll
        for (int r = 0; r < 2; ++r) {
            const int row = b_row + r * 8;
            *reinterpret_cast<float4*>(&Bs[row * 128 + b_col]) =
                *reinterpret_cast<const float4*>(
                    W + (size_t)(kt + row) * NDIM + bn + b_col);
        }
        __syncthreads();

        #pragma unroll
        for (int kk = 0; kk < 16; ++kk) {
            float ra[8], rb[8];
            *reinterpret_cast<float4*>(ra)     = *reinterpret_cast<const float4*>(&As[kk * 132 + tm]);
            *reinterpret_cast<float4*>(ra + 4) = *reinterpret_cast<const float4*>(&As[kk * 132 + tm + 4]);
            *reinterpret_cast<float4*>(rb)     = *reinterpret_cast<const float4*>(&Bs[kk * 128 + tn]);
            *reinterpret_cast<float4*>(rb + 4) = *reinterpret_cast<const float4*>(&Bs[kk * 128 + tn + 4]);
            #pragma unroll
            for (int i = 0; i < 8; ++i)
                #pragma unroll
                for (int j = 0; j < 8; ++j)
                    acc[i][j] = fmaf(ra[i], rb[j], acc[i][j]);
        }
        __syncthreads();
    }

    #pragma unroll
    for (int i = 0; i < 8; ++i) {
        float* zr = g_scratch + (size_t)(bm + tm + i) * NDIM + bn + tn;
        *reinterpret_cast<float4*>(zr)     = make_float4(acc[i][0], acc[i][1], acc[i][2], acc[i][3]);
        *reinterpret_cast<float4*>(zr + 4) = make_float4(acc[i][4], acc[i][5], acc[i][6], acc[i][7]);
    }
}

// ---------------------------------------------------------------------------
// LSTM gate epilogue. Z layout: [B, 4H] with gate order i, f, o, g.
// c_new = c*sigmoid(zf) + tanh(zg)*sigmoid(zi); h_new = tanh(c_new)*sigmoid(zo)
// ---------------------------------------------------------------------------
__device__ __forceinline__ float sigmoidf_(float x) {
    return 1.0f / (1.0f + expf(-x));
}

__global__ __launch_bounds__(256) void lstm_epilogue_kernel(
    const float* __restrict__ c_prev,   // [4096,1024]
    const float* __restrict__ bias,     // [4096] (this layer)
    float* __restrict__ h_out,          // [4096,1024]
    float* __restrict__ c_out,          // [4096,1024]
    float* __restrict__ final_out)      // [4096,1024] or nullptr
{
    const int idx = blockIdx.x * blockDim.x + threadIdx.x;  // 0 .. 4096*1024-1
    const int row = idx >> 10;
    const int j   = idx & 1023;
    const size_t zb = (size_t)row * NDIM + j;

    const float zi = g_scratch[zb]              + bias[j];
    const float zf = g_scratch[zb + 1 * HID]    + bias[1 * HID + j];
    const float zo = g_scratch[zb + 2 * HID]    + bias[2 * HID + j];
    const float zg = g_scratch[zb + 3 * HID]    + bias[3 * HID + j];

    const float ig = sigmoidf_(zi);
    const float fg = sigmoidf_(zf);
    const float og = sigmoidf_(zo);
    const float gg = tanhf(zg);

    const float c_new = c_prev[idx] * fg + gg * ig;
    const float h_new = tanhf(c_new) * og;

    h_out[idx] = h_new;
    c_out[idx] = c_new;
    if (final_out) final_out[idx] = h_new;
}

// ---------------------------------------------------------------------------
// Launch: 4 sequential layers (GEMM + epilogue each), all on stream 0.
// Inputs (metadata order): x, s_h, s_c, W, b.
// Output: [out (4M) | h_new (4x4M) | c_new (4x4M)] floats.
// ---------------------------------------------------------------------------
extern "C" void kernel_launch(void* const* d_in, const int* in_sizes, int n_in,
                              void* d_out, int out_size) {
    const float* x   = (const float*)d_in[0];
    const float* s_h = (const float*)d_in[1];
    const float* s_c = (const float*)d_in[2];
    const float* W   = (const float*)d_in[3];
    const float* b   = (const float*)d_in[4];

    float* out   = (float*)d_out;
    float* hbase = out + (size_t)BATCH * HID;                    // h_new [4,B,H]
    float* cbase = hbase + (size_t)4 * BATCH * HID;              // c_new [4,B,H]

    const size_t layer_state = (size_t)BATCH * HID;              // 4,194,304
    const size_t layer_w     = (size_t)KDIM * NDIM;              // 8,388,608

    dim3 ggrid(NDIM / 128, BATCH / 128);                          // 32 x 32
    const int egrid = (BATCH * HID) / 256;                        // 16384

    for (int l = 0; l < 4; ++l) {
        const float* Xl = (l == 0) ? x : (hbase + (size_t)(l - 1) * layer_state);
        gemm128_kernel<<<ggrid, 256>>>(
            Xl,
            s_h + (size_t)l * layer_state,
            W + (size_t)l * layer_w);
        lstm_epilogue_kernel<<<egrid, 256>>>(
            s_c + (size_t)l * layer_state,
            b + (size_t)l * NDIM,
            hbase + (size_t)l * layer_state,
            cbase + (size_t)l * layer_state,
            (l == 3) ? out : nullptr);
    }
}

// round 8
// speedup vs baseline: 2.1863x; 2.1863x over previous
#include <cuda_runtime.h>
#include <cuda_bf16.h>
#include <math.h>
#include <stdint.h>

// Problem shape (fixed): DEPTH=4, B=4096, H=E=1024, K=2048, N=4H=4096
#define BATCH 4096
#define HID   1024
#define KDIM  2048
#define NDIM  4096

// GEMM tiling
#define BM 128
#define BN 128
#define BK 32
#define STAGES 4
#define ROW_BYTES 80                       // 32 bf16 = 64B payload, padded to 80B (5x16B)
#define TILE_SMEM (128 * ROW_BYTES)        // 10240 B per operand tile
#define STAGE_SMEM (4 * TILE_SMEM)         // Ahi, Alo, Bhi, Blo = 40960 B
#define SMEM_SZ (STAGES * STAGE_SMEM)      // 163840 B

// ---------------------------------------------------------------------------
// Device scratch (no allocations allowed)
// ---------------------------------------------------------------------------
__device__ float         g_scratch[(size_t)BATCH * NDIM];          // Z pre-activations (64 MB)
__device__ __nv_bfloat16 g_Ahi[(size_t)BATCH * KDIM];              // [X|h] hi  (16.8 MB)
__device__ __nv_bfloat16 g_Alo[(size_t)BATCH * KDIM];              // [X|h] lo
__device__ __nv_bfloat16 g_Whi[4][(size_t)NDIM * KDIM];            // W^T hi, [n][k] (67 MB)
__device__ __nv_bfloat16 g_Wlo[4][(size_t)NDIM * KDIM];            // W^T lo

// ---------------------------------------------------------------------------
// PTX helpers (base sm_103 ISA only: cp.async + ldmatrix + mma.sync)
// ---------------------------------------------------------------------------
__device__ __forceinline__ uint32_t smem_u32(const void* p) {
    uint32_t a;
    asm("{ .reg .u64 t; cvta.to.shared.u64 t, %1; cvt.u32.u64 %0, t; }"
        : "=r"(a) : "l"(p));
    return a;
}

__device__ __forceinline__ void cp_async16(uint32_t dst, const void* src) {
    asm volatile("cp.async.cg.shared.global [%0], [%1], 16;"
                 :: "r"(dst), "l"(src) : "memory");
}
__device__ __forceinline__ void cp_commit() {
    asm volatile("cp.async.commit_group;" ::: "memory");
}
__device__ __forceinline__ void cp_wait2() {
    asm volatile("cp.async.wait_group 2;" ::: "memory");
}

__device__ __forceinline__ void ldsm_x4(uint32_t& r0, uint32_t& r1,
                                        uint32_t& r2, uint32_t& r3, uint32_t addr) {
    asm volatile("ldmatrix.sync.aligned.m8n8.x4.shared.b16 {%0,%1,%2,%3}, [%4];"
                 : "=r"(r0), "=r"(r1), "=r"(r2), "=r"(r3) : "r"(addr));
}

__device__ __forceinline__ void mma16816(float* c, const uint32_t* a,
                                         uint32_t b0, uint32_t b1) {
    asm volatile(
        "mma.sync.aligned.m16n8k16.row.col.f32.bf16.bf16.f32 "
        "{%0,%1,%2,%3}, {%4,%5,%6,%7}, {%8,%9}, {%0,%1,%2,%3};"
        : "+f"(c[0]), "+f"(c[1]), "+f"(c[2]), "+f"(c[3])
        : "r"(a[0]), "r"(a[1]), "r"(a[2]), "r"(a[3]), "r"(b0), "r"(b1));
}

// ---------------------------------------------------------------------------
// Conversion kernels (fp32 -> bf16 hi/lo split)
// ---------------------------------------------------------------------------
__device__ __forceinline__ void split_bf16(float v, __nv_bfloat16& hi, __nv_bfloat16& lo) {
    hi = __float2bfloat16(v);
    lo = __float2bfloat16(v - __bfloat162float(hi));
}

// W [4][2048][4096] fp32 -> Wt hi/lo [4][4096][2048] bf16 (transpose, all layers)
__global__ __launch_bounds__(256) void convert_W_kernel(const float* __restrict__ W) {
    __shared__ float t[32][33];
    const int l  = blockIdx.z;
    const int nb = blockIdx.x * 32;
    const int kb = blockIdx.y * 32;
    const int tx = threadIdx.x & 31;
    const int ty = threadIdx.x >> 5;   // 0..7
    const float* Wl = W + (size_t)l * KDIM * NDIM;

    #pragma unroll
    for (int r = 0; r < 4; ++r)
        t[ty + r * 8][tx] = Wl[(size_t)(kb + ty + r * 8) * NDIM + nb + tx];
    __syncthreads();

    #pragma unroll
    for (int r = 0; r < 4; ++r) {
        const int n = nb + ty + r * 8;
        const int k = kb + tx;
        __nv_bfloat16 hb, lb;
        split_bf16(t[tx][ty + r * 8], hb, lb);
        g_Whi[l][(size_t)n * KDIM + k] = hb;
        g_Wlo[l][(size_t)n * KDIM + k] = lb;
    }
}

// A = [X | h] (4096 x 2048) -> g_Ahi / g_Alo
__global__ __launch_bounds__(256) void convert_A_kernel(
    const float* __restrict__ X, const float* __restrict__ Hh) {
    const int idx = blockIdx.x * 256 + threadIdx.x;    // quads
    const int m = idx >> 9;                            // 512 quads per row
    const int k = (idx & 511) << 2;
    const float* src = (k < HID) ? (X + (size_t)m * HID + k)
                                 : (Hh + (size_t)m * HID + (k - HID));
    const float4 v = *reinterpret_cast<const float4*>(src);
    __nv_bfloat16 h0, l0, h1, l1, h2, l2, h3, l3;
    split_bf16(v.x, h0, l0); split_bf16(v.y, h1, l1);
    split_bf16(v.z, h2, l2); split_bf16(v.w, h3, l3);
    const size_t o = (size_t)m * KDIM + k;
    *reinterpret_cast<__nv_bfloat162*>(&g_Ahi[o])     = __nv_bfloat162(h0, h1);
    *reinterpret_cast<__nv_bfloat162*>(&g_Ahi[o + 2]) = __nv_bfloat162(h2, h3);
    *reinterpret_cast<__nv_bfloat162*>(&g_Alo[o])     = __nv_bfloat162(l0, l1);
    *reinterpret_cast<__nv_bfloat162*>(&g_Alo[o + 2]) = __nv_bfloat162(l2, l3);
}

// ---------------------------------------------------------------------------
// HMMA GEMM: Z[4096,4096] = A(4096x2048) @ Wt^T, split-precision bf16.
// CTA 128x128, BK=32, 4-stage cp.async pipeline, 8 warps (2m x 4n), warp 64x32.
// Per k16 per warp: 48 x mma.sync.m16n8k16 (AhiBhi + AhiBlo + AloBhi).
// ---------------------------------------------------------------------------
__global__ __launch_bounds__(256, 1) void gemm_mma_kernel(int layer, float* __restrict__ Z) {
    extern __shared__ __align__(128) char smem[];
    const uint32_t sb = smem_u32(smem);
    const int tid  = threadIdx.x;
    const int wid  = tid >> 5;
    const int lane = tid & 31;
    const int bm = blockIdx.x * BM;
    const int bn = blockIdx.y * BN;

    const int wm = (wid & 1) * 64;     // warp m-offset within CTA tile
    const int wn = (wid >> 1) * 32;    // warp n-offset

    const __nv_bfloat16* Ahi_b = g_Ahi + (size_t)bm * KDIM;
    const __nv_bfloat16* Alo_b = g_Alo + (size_t)bm * KDIM;
    const __nv_bfloat16* Bhi_b = g_Whi[layer] + (size_t)bn * KDIM;
    const __nv_bfloat16* Blo_b = g_Wlo[layer] + (size_t)bn * KDIM;

    // cp.async mapping: per tile, thread loads row tid>>1, chunks (tid&1)*2, +1
    const int ld_row = tid >> 1;
    const int ld_c0  = (tid & 1) * 2;

    auto load_stage = [&](int s, int kt /*k16x2 step: k base = kt*BK*/) {
        const __nv_bfloat16* srcs[4] = {Ahi_b, Alo_b, Bhi_b, Blo_b};
        const uint32_t sbase = sb + s * STAGE_SMEM;
        const int kbase = kt * BK + ld_c0 * 8;
        #pragma unroll
        for (int t = 0; t < 4; ++t) {
            const __nv_bfloat16* src = srcs[t] + (size_t)ld_row * KDIM + kbase;
            const uint32_t dst = sbase + t * TILE_SMEM + ld_row * ROW_BYTES + ld_c0 * 16;
            cp_async16(dst, src);
            cp_async16(dst + 16, src + 8);
        }
    };

    float acc[4][4][4];
    #pragma unroll
    for (int i = 0; i < 4; ++i)
        #pragma unroll
        for (int j = 0; j < 4; ++j)
            #pragma unroll
            for (int q = 0; q < 4; ++q) acc[i][j][q] = 0.0f;

    // ldmatrix lane addressing (80B row stride: conflict-free 8-row groups)
    // A frag (m16 x k16): rows (lane&15), chunk +(lane>>4)
    const uint32_t a_off = (uint32_t)((wm + (lane & 15)) * ROW_BYTES + (lane >> 4) * 16);
    // B frag (2 x n8 x k16): rows (lane&7) + ((lane>>4)&1)*8, chunk +((lane>>3)&1)
    const uint32_t b_off = (uint32_t)((wn + (lane & 7) + ((lane >> 4) & 1) * 8) * ROW_BYTES
                                      + ((lane >> 3) & 1) * 16);

    const int NITER = KDIM / BK;   // 64

    #pragma unroll
    for (int s = 0; s < STAGES - 1; ++s) {   // prologue: stages 0,1,2
        load_stage(s, s);
        cp_commit();
    }

    #pragma unroll 1
    for (int kt = 0; kt < NITER; ++kt) {
        cp_wait2();
        __syncthreads();

        if (kt + STAGES - 1 < NITER)
            load_stage((kt + STAGES - 1) & (STAGES - 1), kt + STAGES - 1);
        cp_commit();

        const uint32_t st = sb + (kt & (STAGES - 1)) * STAGE_SMEM;
        const uint32_t sAhi = st + a_off;
        const uint32_t sAlo = sAhi + TILE_SMEM;
        const uint32_t sBhi = st + 2 * TILE_SMEM + b_off;
        const uint32_t sBlo = sBhi + TILE_SMEM;

        #pragma unroll
        for (int h = 0; h < 2; ++h) {        // two k16 halves of BK=32
            uint32_t ah[4][4], al[4][4];
            #pragma unroll
            for (int mi = 0; mi < 4; ++mi) {
                const uint32_t ao = (uint32_t)(mi * 16 * ROW_BYTES + h * 32);
                ldsm_x4(ah[mi][0], ah[mi][1], ah[mi][2], ah[mi][3], sAhi + ao);
                ldsm_x4(al[mi][0], al[mi][1], al[mi][2], al[mi][3], sAlo + ao);
            }
            uint32_t bh[2][4], bl[2][4];
            #pragma unroll
            for (int nb = 0; nb < 2; ++nb) {
                const uint32_t bo = (uint32_t)(nb * 16 * ROW_BYTES + h * 32);
                ldsm_x4(bh[nb][0], bh[nb][1], bh[nb][2], bh[nb][3], sBhi + bo);
                ldsm_x4(bl[nb][0], bl[nb][1], bl[nb][2], bl[nb][3], sBlo + bo);
            }
            #pragma unroll
            for (int mi = 0; mi < 4; ++mi) {
                #pragma unroll
                for (int nj = 0; nj < 4; ++nj) {
                    const int nb = nj >> 1, hf = (nj & 1) * 2;
                    mma16816(acc[mi][nj], ah[mi], bh[nb][hf], bh[nb][hf + 1]);
                    mma16816(acc[mi][nj], ah[mi], bl[nb][hf], bl[nb][hf + 1]);
                    mma16816(acc[mi][nj], al[mi], bh[nb][hf], bh[nb][hf + 1]);
                }
            }
        }
        __syncthreads();
    }

    // Epilogue: write Z tile. Thread holds (m = t/4, n = 2*(t%4)) pattern per frag.
    const int em = bm + wm + (lane >> 2);
    const int en = bn + wn + (lane & 3) * 2;
    #pragma unroll
    for (int mi = 0; mi < 4; ++mi) {
        #pragma unroll
        for (int nj = 0; nj < 4; ++nj) {
            float* z0 = Z + (size_t)(em + mi * 16) * NDIM + en + nj * 8;
            float* z1 = z0 + (size_t)8 * NDIM;
            *reinterpret_cast<float2*>(z0) = make_float2(acc[mi][nj][0], acc[mi][nj][1]);
            *reinterpret_cast<float2*>(z1) = make_float2(acc[mi][nj][2], acc[mi][nj][3]);
        }
    }
}

// ---------------------------------------------------------------------------
// LSTM gate epilogue. Z gate order: i, f, o, g.
// ---------------------------------------------------------------------------
__device__ __forceinline__ float sigmoidf_(float x) { return 1.0f / (1.0f + expf(-x)); }

__global__ __launch_bounds__(256) void lstm_epilogue_kernel(
    const float* __restrict__ c_prev, const float* __restrict__ bias,
    float* __restrict__ h_out, float* __restrict__ c_out,
    float* __restrict__ final_out) {
    const int idx = blockIdx.x * blockDim.x + threadIdx.x;
    const int row = idx >> 10;
    const int j   = idx & 1023;
    const size_t zb = (size_t)row * NDIM + j;

    const float zi = g_scratch[zb]           + bias[j];
    const float zf = g_scratch[zb + 1 * HID] + bias[1 * HID + j];
    const float zo = g_scratch[zb + 2 * HID] + bias[2 * HID + j];
    const float zg = g_scratch[zb + 3 * HID] + bias[3 * HID + j];

    const float ig = sigmoidf_(zi);
    const float fg = sigmoidf_(zf);
    const float og = sigmoidf_(zo);
    const float gg = tanhf(zg);

    const float c_new = c_prev[idx] * fg + gg * ig;
    const float h_new = tanhf(c_new) * og;

    h_out[idx] = h_new;
    c_out[idx] = c_new;
    if (final_out) final_out[idx] = h_new;
}

// ---------------------------------------------------------------------------
// Launch. Inputs: x, s_h, s_c, W, b. Output: [out | h_new[4] | c_new[4]].
// ---------------------------------------------------------------------------
extern "C" void kernel_launch(void* const* d_in, const int* in_sizes, int n_in,
                              void* d_out, int out_size) {
    const float* x   = (const float*)d_in[0];
    const float* s_h = (const float*)d_in[1];
    const float* s_c = (const float*)d_in[2];
    const float* W   = (const float*)d_in[3];
    const float* b   = (const float*)d_in[4];

    float* out   = (float*)d_out;
    float* hbase = out + (size_t)BATCH * HID;
    float* cbase = hbase + (size_t)4 * BATCH * HID;

    const size_t layer_state = (size_t)BATCH * HID;

    cudaFuncSetAttribute(gemm_mma_kernel,
                         cudaFuncAttributeMaxDynamicSharedMemorySize, SMEM_SZ);

    float* Zp;
    cudaGetSymbolAddress((void**)&Zp, g_scratch);

    // W -> transposed hi/lo bf16, all layers
    convert_W_kernel<<<dim3(NDIM / 32, KDIM / 32, 4), 256>>>(W);

    dim3 ggrid(BATCH / BM, NDIM / BN);             // x-major wave shares bn (W reuse)
    const int agrid = (BATCH * KDIM / 4) / 256;    // 8192
    const int egrid = (BATCH * HID) / 256;         // 16384

    for (int l = 0; l < 4; ++l) {
        const float* Xl = (l == 0) ? x : (hbase + (size_t)(l - 1) * layer_state);
        convert_A_kernel<<<agrid, 256>>>(Xl, s_h + (size_t)l * layer_state);
        gemm_mma_kernel<<<ggrid, 256, SMEM_SZ>>>(l, Zp);
        lstm_epilogue_kernel<<<egrid, 256>>>(
            s_c + (size_t)l * layer_state,
            b + (size_t)l * NDIM,
            hbase + (size_t)l * layer_state,
            cbase + (size_t)l * layer_state,
            (l == 3) ? out : nullptr);
    }
}

// round 12
// speedup vs baseline: 3.0075x; 1.3756x over previous
#include <cuda_runtime.h>
#include <cuda_fp16.h>
#include <math.h>
#include <stdint.h>

// Problem shape (fixed): DEPTH=4, B=4096, H=E=1024, K=2048, N=4H=4096
#define BATCH 4096
#define HID   1024
#define KDIM  2048
#define NDIM  4096

// GEMM tiling
#define BM 128
#define BN 128
#define BK 32
#define STAGES 4
#define ROW_BYTES 80                       // 32 fp16 = 64B payload, padded to 80B (5x16B)
#define TILE_SMEM (128 * ROW_BYTES)        // 10240 B per operand tile
#define STAGE_SMEM (3 * TILE_SMEM)         // Ah, Al, Wh = 30720 B
#define SMEM_SZ (STAGES * STAGE_SMEM)      // 122880 B

// ---------------------------------------------------------------------------
// Device scratch (no allocations allowed)
// ---------------------------------------------------------------------------
__device__ float  g_scratch[(size_t)BATCH * NDIM];            // Z pre-activations (64 MB)
__device__ __half g_Ah[4][(size_t)BATCH * KDIM];              // per-layer [X|h] hi (64 MB)
__device__ __half g_Al[4][(size_t)BATCH * KDIM];              // per-layer [X|h] lo (64 MB)
__device__ __half g_Wh[4][(size_t)NDIM * KDIM];               // W^T fp16, [n][k]  (64 MB)

// ---------------------------------------------------------------------------
// PTX helpers (base sm_103 ISA: cp.async + ldmatrix + mma.sync)
// ---------------------------------------------------------------------------
__device__ __forceinline__ uint32_t smem_u32(const void* p) {
    uint32_t a;
    asm("{ .reg .u64 t; cvta.to.shared.u64 t, %1; cvt.u32.u64 %0, t; }"
        : "=r"(a) : "l"(p));
    return a;
}

__device__ __forceinline__ void cp_async16(uint32_t dst, const void* src) {
    asm volatile("cp.async.cg.shared.global [%0], [%1], 16;"
                 :: "r"(dst), "l"(src) : "memory");
}
__device__ __forceinline__ void cp_commit() {
    asm volatile("cp.async.commit_group;" ::: "memory");
}
__device__ __forceinline__ void cp_wait2() {
    asm volatile("cp.async.wait_group 2;" ::: "memory");
}

__device__ __forceinline__ void ldsm_x4(uint32_t& r0, uint32_t& r1,
                                        uint32_t& r2, uint32_t& r3, uint32_t addr) {
    asm volatile("ldmatrix.sync.aligned.m8n8.x4.shared.b16 {%0,%1,%2,%3}, [%4];"
                 : "=r"(r0), "=r"(r1), "=r"(r2), "=r"(r3) : "r"(addr));
}

__device__ __forceinline__ void mma16816(float* c, const uint32_t* a,
                                         uint32_t b0, uint32_t b1) {
    asm volatile(
        "mma.sync.aligned.m16n8k16.row.col.f32.f16.f16.f32 "
        "{%0,%1,%2,%3}, {%4,%5,%6,%7}, {%8,%9}, {%0,%1,%2,%3};"
        : "+f"(c[0]), "+f"(c[1]), "+f"(c[2]), "+f"(c[3])
        : "r"(a[0]), "r"(a[1]), "r"(a[2]), "r"(a[3]), "r"(b0), "r"(b1));
}

// ---------------------------------------------------------------------------
// fp32 -> fp16 hi/lo split
// ---------------------------------------------------------------------------
__device__ __forceinline__ void split_fp16(float v, __half& hi, __half& lo) {
    hi = __float2half(v);
    lo = __float2half(v - __half2float(hi));
}

// W [4][2048][4096] fp32 -> Wt fp16 [4][4096][2048] (transpose, all layers)
__global__ __launch_bounds__(256) void convert_W_kernel(const float* __restrict__ W) {
    __shared__ float t[32][33];
    const int l  = blockIdx.z;
    const int nb = blockIdx.x * 32;
    const int kb = blockIdx.y * 32;
    const int tx = threadIdx.x & 31;
    const int ty = threadIdx.x >> 5;   // 0..7
    const float* Wl = W + (size_t)l * KDIM * NDIM;

    #pragma unroll
    for (int r = 0; r < 4; ++r)
        t[ty + r * 8][tx] = Wl[(size_t)(kb + ty + r * 8) * NDIM + nb + tx];
    __syncthreads();

    #pragma unroll
    for (int r = 0; r < 4; ++r) {
        const int n = nb + ty + r * 8;
        const int k = kb + tx;
        g_Wh[l][(size_t)n * KDIM + k] = __float2half(t[tx][ty + r * 8]);
    }
}

// x [4096,1024] -> A[0] cols 0..1023 (hi/lo)
__global__ __launch_bounds__(256) void prep_x_kernel(const float* __restrict__ X) {
    const int idx = blockIdx.x * 256 + threadIdx.x;   // quads over 4096x1024
    const int m = idx >> 8;                           // 256 quads per row
    const int k = (idx & 255) << 2;
    const float4 v = *reinterpret_cast<const float4*>(X + (size_t)m * HID + k);
    __half h0, l0, h1, l1, h2, l2, h3, l3;
    split_fp16(v.x, h0, l0); split_fp16(v.y, h1, l1);
    split_fp16(v.z, h2, l2); split_fp16(v.w, h3, l3);
    const size_t o = (size_t)m * KDIM + k;
    *reinterpret_cast<__half2*>(&g_Ah[0][o])     = __half2(h0, h1);
    *reinterpret_cast<__half2*>(&g_Ah[0][o + 2]) = __half2(h2, h3);
    *reinterpret_cast<__half2*>(&g_Al[0][o])     = __half2(l0, l1);
    *reinterpret_cast<__half2*>(&g_Al[0][o + 2]) = __half2(l2, l3);
}

// s_h [4][4096][1024] -> A[l] cols 1024..2047 (hi/lo), all layers
__global__ __launch_bounds__(256) void prep_sh_kernel(const float* __restrict__ SH) {
    const int l   = blockIdx.z;
    const int idx = blockIdx.x * 256 + threadIdx.x;
    const int m = idx >> 8;
    const int k = (idx & 255) << 2;
    const float4 v = *reinterpret_cast<const float4*>(
        SH + (size_t)l * BATCH * HID + (size_t)m * HID + k);
    __half h0, l0, h1, l1, h2, l2, h3, l3;
    split_fp16(v.x, h0, l0); split_fp16(v.y, h1, l1);
    split_fp16(v.z, h2, l2); split_fp16(v.w, h3, l3);
    const size_t o = (size_t)m * KDIM + HID + k;
    *reinterpret_cast<__half2*>(&g_Ah[l][o])     = __half2(h0, h1);
    *reinterpret_cast<__half2*>(&g_Ah[l][o + 2]) = __half2(h2, h3);
    *reinterpret_cast<__half2*>(&g_Al[l][o])     = __half2(l0, l1);
    *reinterpret_cast<__half2*>(&g_Al[l][o + 2]) = __half2(l2, l3);
}

// ---------------------------------------------------------------------------
// HMMA GEMM: Z[4096,4096] = A(4096x2048) @ Wt^T, fp16 2-term split.
// CTA 128x128, BK=32, 4-stage cp.async pipeline, 8 warps (2m x 4n), warp 64x32.
// Per k16 per warp: 32 x mma.sync.m16n8k16 (Ah*Wh + Al*Wh).
// ---------------------------------------------------------------------------
__global__ __launch_bounds__(256, 1) void gemm_mma_kernel(int layer, float* __restrict__ Z) {
    extern __shared__ __align__(128) char smem[];
    const uint32_t sb = smem_u32(smem);
    const int tid  = threadIdx.x;
    const int wid  = tid >> 5;
    const int lane = tid & 31;
    const int bm = blockIdx.x * BM;
    const int bn = blockIdx.y * BN;

    const int wm = (wid & 1) * 64;
    const int wn = (wid >> 1) * 32;

    const __half* Ah_b = g_Ah[layer] + (size_t)bm * KDIM;
    const __half* Al_b = g_Al[layer] + (size_t)bm * KDIM;
    const __half* Wh_b = g_Wh[layer] + (size_t)bn * KDIM;

    // cp.async mapping: per tile, thread loads row tid>>1, chunks (tid&1)*2, +1
    const int ld_row = tid >> 1;
    const int ld_c0  = (tid & 1) * 2;

    auto load_stage = [&](int s, int kt) {
        const __half* srcs[3] = {Ah_b, Al_b, Wh_b};
        const uint32_t sbase = sb + s * STAGE_SMEM;
        const int kbase = kt * BK + ld_c0 * 8;
        #pragma unroll
        for (int t = 0; t < 3; ++t) {
            const __half* src = srcs[t] + (size_t)ld_row * KDIM + kbase;
            const uint32_t dst = sbase + t * TILE_SMEM + ld_row * ROW_BYTES + ld_c0 * 16;
            cp_async16(dst, src);
            cp_async16(dst + 16, src + 8);
        }
    };

    float acc[4][4][4];
    #pragma unroll
    for (int i = 0; i < 4; ++i)
        #pragma unroll
        for (int j = 0; j < 4; ++j)
            #pragma unroll
            for (int q = 0; q < 4; ++q) acc[i][j][q] = 0.0f;

    // ldmatrix lane addressing (80B row stride: conflict-free 8-row groups)
    const uint32_t a_off = (uint32_t)((wm + (lane & 15)) * ROW_BYTES + (lane >> 4) * 16);
    const uint32_t b_off = (uint32_t)((wn + (lane & 7) + ((lane >> 4) & 1) * 8) * ROW_BYTES
                                      + ((lane >> 3) & 1) * 16);

    const int NITER = KDIM / BK;   // 64

    #pragma unroll
    for (int s = 0; s < STAGES - 1; ++s) {
        load_stage(s, s);
        cp_commit();
    }

    #pragma unroll 1
    for (int kt = 0; kt < NITER; ++kt) {
        cp_wait2();
        __syncthreads();   // also orders iter kt-1's ldsm reads before stage reuse below

        if (kt + STAGES - 1 < NITER)
            load_stage((kt + STAGES - 1) & (STAGES - 1), kt + STAGES - 1);
        cp_commit();

        const uint32_t st  = sb + (kt & (STAGES - 1)) * STAGE_SMEM;
        const uint32_t sAh = st + a_off;
        const uint32_t sAl = sAh + TILE_SMEM;
        const uint32_t sBh = st + 2 * TILE_SMEM + b_off;

        #pragma unroll
        for (int h = 0; h < 2; ++h) {        // two k16 halves of BK=32
            uint32_t ah[4][4], al[4][4];
            #pragma unroll
            for (int mi = 0; mi < 4; ++mi) {
                const uint32_t ao = (uint32_t)(mi * 16 * ROW_BYTES + h * 32);
                ldsm_x4(ah[mi][0], ah[mi][1], ah[mi][2], ah[mi][3], sAh + ao);
                ldsm_x4(al[mi][0], al[mi][1], al[mi][2], al[mi][3], sAl + ao);
            }
            uint32_t bh[2][4];
            #pragma unroll
            for (int nb = 0; nb < 2; ++nb) {
                const uint32_t bo = (uint32_t)(nb * 16 * ROW_BYTES + h * 32);
                ldsm_x4(bh[nb][0], bh[nb][1], bh[nb][2], bh[nb][3], sBh + bo);
            }
            #pragma unroll
            for (int mi = 0; mi < 4; ++mi) {
                #pragma unroll
                for (int nj = 0; nj < 4; ++nj) {
                    const int nb = nj >> 1, hf = (nj & 1) * 2;
                    mma16816(acc[mi][nj], ah[mi], bh[nb][hf], bh[nb][hf + 1]);
                    mma16816(acc[mi][nj], al[mi], bh[nb][hf], bh[nb][hf + 1]);
                }
            }
        }
    }

    // Epilogue: write Z tile
    const int em = bm + wm + (lane >> 2);
    const int en = bn + wn + (lane & 3) * 2;
    #pragma unroll
    for (int mi = 0; mi < 4; ++mi) {
        #pragma unroll
        for (int nj = 0; nj < 4; ++nj) {
            float* z0 = Z + (size_t)(em + mi * 16) * NDIM + en + nj * 8;
            float* z1 = z0 + (size_t)8 * NDIM;
            *reinterpret_cast<float2*>(z0) = make_float2(acc[mi][nj][0], acc[mi][nj][1]);
            *reinterpret_cast<float2*>(z1) = make_float2(acc[mi][nj][2], acc[mi][nj][3]);
        }
    }
}

// ---------------------------------------------------------------------------
// LSTM gate epilogue. Z gate order: i, f, o, g. Also writes the fp16 hi/lo
// split of h_new into the NEXT layer's A buffer (cols 0..1023).
// ---------------------------------------------------------------------------
__device__ __forceinline__ float sigmoidf_(float x) { return 1.0f / (1.0f + expf(-x)); }

__global__ __launch_bounds__(256) void lstm_epilogue_kernel(
    const float* __restrict__ c_prev, const float* __restrict__ bias,
    float* __restrict__ h_out, float* __restrict__ c_out,
    float* __restrict__ final_out,
    __half* __restrict__ nextAh, __half* __restrict__ nextAl) {
    const int idx = blockIdx.x * blockDim.x + threadIdx.x;
    const int row = idx >> 10;
    const int j   = idx & 1023;
    const size_t zb = (size_t)row * NDIM + j;

    const float zi = g_scratch[zb]           + bias[j];
    const float zf = g_scratch[zb + 1 * HID] + bias[1 * HID + j];
    const float zo = g_scratch[zb + 2 * HID] + bias[2 * HID + j];
    const float zg = g_scratch[zb + 3 * HID] + bias[3 * HID + j];

    const float ig = sigmoidf_(zi);
    const float fg = sigmoidf_(zf);
    const float og = sigmoidf_(zo);
    const float gg = tanhf(zg);

    const float c_new = c_prev[idx] * fg + gg * ig;
    const float h_new = tanhf(c_new) * og;

    h_out[idx] = h_new;
    c_out[idx] = c_new;
    if (final_out) final_out[idx] = h_new;

    if (nextAh) {
        __half hh, hl;
        split_fp16(h_new, hh, hl);
        const size_t ao = (size_t)row * KDIM + j;
        nextAh[ao] = hh;
        nextAl[ao] = hl;
    }
}

// ---------------------------------------------------------------------------
// Launch. Inputs: x, s_h, s_c, W, b. Output: [out | h_new[4] | c_new[4]].
// ---------------------------------------------------------------------------
extern "C" void kernel_launch(void* const* d_in, const int* in_sizes, int n_in,
                              void* d_out, int out_size) {
    const float* x   = (const float*)d_in[0];
    const float* s_h = (const float*)d_in[1];
    const float* s_c = (const float*)d_in[2];
    const float* W   = (const float*)d_in[3];
    const float* b   = (const float*)d_in[4];

    float* out   = (float*)d_out;
    float* hbase = out + (size_t)BATCH * HID;
    float* cbase = hbase + (size_t)4 * BATCH * HID;

    const size_t layer_state = (size_t)BATCH * HID;

    cudaFuncSetAttribute(gemm_mma_kernel,
                         cudaFuncAttributeMaxDynamicSharedMemorySize, SMEM_SZ);

    float* Zp;
    cudaGetSymbolAddress((void**)&Zp, g_scratch);
    __half* Ahp[4];
    __half* Alp[4];
    {
        __half* base_h; __half* base_l;
        cudaGetSymbolAddress((void**)&base_h, g_Ah);
        cudaGetSymbolAddress((void**)&base_l, g_Al);
        for (int l = 0; l < 4; ++l) {
            Ahp[l] = base_h + (size_t)l * BATCH * KDIM;
            Alp[l] = base_l + (size_t)l * BATCH * KDIM;
        }
    }

    // Upfront conversions: W (all layers), x -> A0, s_h -> A[l] (cols >= 1024)
    convert_W_kernel<<<dim3(NDIM / 32, KDIM / 32, 4), 256>>>(W);
    const int pgrid = (BATCH * HID / 4) / 256;   // 4096
    prep_x_kernel<<<pgrid, 256>>>(x);
    prep_sh_kernel<<<dim3(pgrid, 1, 4), 256>>>(s_h);

    dim3 ggrid(BATCH / BM, NDIM / BN);           // x-major wave shares bn (W reuse)
    const int egrid = (BATCH * HID) / 256;       // 16384

    for (int l = 0; l < 4; ++l) {
        gemm_mma_kernel<<<ggrid, 256, SMEM_SZ>>>(l, Zp);
        lstm_epilogue_kernel<<<egrid, 256>>>(
            s_c + (size_t)l * layer_state,
            b + (size_t)l * NDIM,
            hbase + (size_t)l * layer_state,
            cbase + (size_t)l * layer_state,
            (l == 3) ? out : nullptr,
            (l < 3) ? Ahp[l + 1] : nullptr,
            (l < 3) ? Alp[l + 1] : nullptr);
    }
}

// round 16
// speedup vs baseline: 3.1925x; 1.0615x over previous
#include <cuda_runtime.h>
#include <cuda_fp16.h>
#include <math.h>
#include <stdint.h>

// Problem shape (fixed): DEPTH=4, B=4096, H=E=1024, K=2048, N=4H=4096
#define BATCH 4096
#define HID   1024
#define KDIM  2048
#define NDIM  4096

// GEMM tiling
#define BM 128
#define BN 128
#define BK 32
#define STAGES 3
#define ROW_BYTES 80                       // 32 fp16 = 64B payload, padded to 80B (5x16B)
#define TILE_SMEM (128 * ROW_BYTES)        // 10240 B per operand tile
#define STAGE_SMEM (3 * TILE_SMEM)         // Ah, Al, Wh = 30720 B
#define SMEM_SZ (STAGES * STAGE_SMEM)      // 92160 B -> 2 CTAs/SM

// ---------------------------------------------------------------------------
// Device scratch (no allocations allowed)
// ---------------------------------------------------------------------------
__device__ float  g_scratch[(size_t)BATCH * NDIM];            // Z pre-activations (64 MB)
__device__ __half g_Ah[4][(size_t)BATCH * KDIM];              // per-layer [X|h] hi (64 MB)
__device__ __half g_Al[4][(size_t)BATCH * KDIM];              // per-layer [X|h] lo (64 MB)
__device__ __half g_Wh[4][(size_t)NDIM * KDIM];               // W^T fp16, [n][k]  (64 MB)

// ---------------------------------------------------------------------------
// PTX helpers (base sm_103 ISA: cp.async + ldmatrix + mma.sync)
// ---------------------------------------------------------------------------
__device__ __forceinline__ uint32_t smem_u32(const void* p) {
    uint32_t a;
    asm("{ .reg .u64 t; cvta.to.shared.u64 t, %1; cvt.u32.u64 %0, t; }"
        : "=r"(a) : "l"(p));
    return a;
}

__device__ __forceinline__ void cp_async16(uint32_t dst, const void* src) {
    asm volatile("cp.async.cg.shared.global [%0], [%1], 16;"
                 :: "r"(dst), "l"(src) : "memory");
}
__device__ __forceinline__ void cp_commit() {
    asm volatile("cp.async.commit_group;" ::: "memory");
}
__device__ __forceinline__ void cp_wait1() {
    asm volatile("cp.async.wait_group 1;" ::: "memory");
}

__device__ __forceinline__ void ldsm_x4(uint32_t& r0, uint32_t& r1,
                                        uint32_t& r2, uint32_t& r3, uint32_t addr) {
    asm volatile("ldmatrix.sync.aligned.m8n8.x4.shared.b16 {%0,%1,%2,%3}, [%4];"
                 : "=r"(r0), "=r"(r1), "=r"(r2), "=r"(r3) : "r"(addr));
}

__device__ __forceinline__ void mma16816(float* c, const uint32_t* a,
                                         uint32_t b0, uint32_t b1) {
    asm volatile(
        "mma.sync.aligned.m16n8k16.row.col.f32.f16.f16.f32 "
        "{%0,%1,%2,%3}, {%4,%5,%6,%7}, {%8,%9}, {%0,%1,%2,%3};"
        : "+f"(c[0]), "+f"(c[1]), "+f"(c[2]), "+f"(c[3])
        : "r"(a[0]), "r"(a[1]), "r"(a[2]), "r"(a[3]), "r"(b0), "r"(b1));
}

// ---------------------------------------------------------------------------
// fp32 -> fp16 hi/lo split
// ---------------------------------------------------------------------------
__device__ __forceinline__ void split_fp16(float v, __half& hi, __half& lo) {
    hi = __float2half(v);
    lo = __float2half(v - __half2float(hi));
}

// W [4][2048][4096] fp32 -> Wt fp16 [4][4096][2048] (transpose, all layers)
__global__ __launch_bounds__(256) void convert_W_kernel(const float* __restrict__ W) {
    __shared__ float t[32][33];
    const int l  = blockIdx.z;
    const int nb = blockIdx.x * 32;
    const int kb = blockIdx.y * 32;
    const int tx = threadIdx.x & 31;
    const int ty = threadIdx.x >> 5;   // 0..7
    const float* Wl = W + (size_t)l * KDIM * NDIM;

    #pragma unroll
    for (int r = 0; r < 4; ++r)
        t[ty + r * 8][tx] = Wl[(size_t)(kb + ty + r * 8) * NDIM + nb + tx];
    __syncthreads();

    #pragma unroll
    for (int r = 0; r < 4; ++r) {
        const int n = nb + ty + r * 8;
        const int k = kb + tx;
        g_Wh[l][(size_t)n * KDIM + k] = __float2half(t[tx][ty + r * 8]);
    }
}

// x [4096,1024] -> A[0] cols 0..1023 (hi/lo)
__global__ __launch_bounds__(256) void prep_x_kernel(const float* __restrict__ X) {
    const int idx = blockIdx.x * 256 + threadIdx.x;   // quads over 4096x1024
    const int m = idx >> 8;                           // 256 quads per row
    const int k = (idx & 255) << 2;
    const float4 v = *reinterpret_cast<const float4*>(X + (size_t)m * HID + k);
    __half h0, l0, h1, l1, h2, l2, h3, l3;
    split_fp16(v.x, h0, l0); split_fp16(v.y, h1, l1);
    split_fp16(v.z, h2, l2); split_fp16(v.w, h3, l3);
    const size_t o = (size_t)m * KDIM + k;
    *reinterpret_cast<__half2*>(&g_Ah[0][o])     = __half2(h0, h1);
    *reinterpret_cast<__half2*>(&g_Ah[0][o + 2]) = __half2(h2, h3);
    *reinterpret_cast<__half2*>(&g_Al[0][o])     = __half2(l0, l1);
    *reinterpret_cast<__half2*>(&g_Al[0][o + 2]) = __half2(l2, l3);
}

// s_h [4][4096][1024] -> A[l] cols 1024..2047 (hi/lo), all layers
__global__ __launch_bounds__(256) void prep_sh_kernel(const float* __restrict__ SH) {
    const int l   = blockIdx.z;
    const int idx = blockIdx.x * 256 + threadIdx.x;
    const int m = idx >> 8;
    const int k = (idx & 255) << 2;
    const float4 v = *reinterpret_cast<const float4*>(
        SH + (size_t)l * BATCH * HID + (size_t)m * HID + k);
    __half h0, l0, h1, l1, h2, l2, h3, l3;
    split_fp16(v.x, h0, l0); split_fp16(v.y, h1, l1);
    split_fp16(v.z, h2, l2); split_fp16(v.w, h3, l3);
    const size_t o = (size_t)m * KDIM + HID + k;
    *reinterpret_cast<__half2*>(&g_Ah[l][o])     = __half2(h0, h1);
    *reinterpret_cast<__half2*>(&g_Ah[l][o + 2]) = __half2(h2, h3);
    *reinterpret_cast<__half2*>(&g_Al[l][o])     = __half2(l0, l1);
    *reinterpret_cast<__half2*>(&g_Al[l][o + 2]) = __half2(l2, l3);
}

// ---------------------------------------------------------------------------
// HMMA GEMM: Z[4096,4096] = A(4096x2048) @ Wt^T, fp16 2-term split.
// CTA 128x128, BK=32, 3-stage cp.async pipeline, 2 CTAs/SM, 8 warps (2m x 4n).
// Per k16 per warp: 32 x mma.sync.m16n8k16 (Ah*Wh + Al*Wh).
// Steady state: commit prefetch FIRST, then wait_group 1 -> the group that
// wrote the stage about to be computed on is provably retired.
// ---------------------------------------------------------------------------
__global__ __launch_bounds__(256, 2) void gemm_mma_kernel(int layer, float* __restrict__ Z) {
    extern __shared__ __align__(128) char smem[];
    const uint32_t sb = smem_u32(smem);
    const int tid  = threadIdx.x;
    const int wid  = tid >> 5;
    const int lane = tid & 31;
    const int bm = blockIdx.x * BM;
    const int bn = blockIdx.y * BN;

    const int wm = (wid & 1) * 64;
    const int wn = (wid >> 1) * 32;

    const __half* Ah_b = g_Ah[layer] + (size_t)bm * KDIM;
    const __half* Al_b = g_Al[layer] + (size_t)bm * KDIM;
    const __half* Wh_b = g_Wh[layer] + (size_t)bn * KDIM;

    // cp.async mapping: per tile, thread loads row tid>>1, chunks (tid&1)*2, +1
    const int ld_row = tid >> 1;
    const int ld_c0  = (tid & 1) * 2;

    auto load_stage = [&](int s, int kt) {
        const __half* srcs[3] = {Ah_b, Al_b, Wh_b};
        const uint32_t sbase = sb + s * STAGE_SMEM;
        const int kbase = kt * BK + ld_c0 * 8;
        #pragma unroll
        for (int t = 0; t < 3; ++t) {
            const __half* src = srcs[t] + (size_t)ld_row * KDIM + kbase;
            const uint32_t dst = sbase + t * TILE_SMEM + ld_row * ROW_BYTES + ld_c0 * 16;
            cp_async16(dst, src);
            cp_async16(dst + 16, src + 8);
        }
    };

    float acc[4][4][4];
    #pragma unroll
    for (int i = 0; i < 4; ++i)
        #pragma unroll
        for (int j = 0; j < 4; ++j)
            #pragma unroll
            for (int q = 0; q < 4; ++q) acc[i][j][q] = 0.0f;

    // ldmatrix lane addressing (80B row stride: conflict-free 8-row groups)
    const uint32_t a_off = (uint32_t)((wm + (lane & 15)) * ROW_BYTES + (lane >> 4) * 16);
    const uint32_t b_off = (uint32_t)((wn + (lane & 7) + ((lane >> 4) & 1) * 8) * ROW_BYTES
                                      + ((lane >> 3) & 1) * 16);

    const int NITER = KDIM / BK;   // 64

    load_stage(0, 0); cp_commit();   // group 0 -> stage 0
    load_stage(1, 1); cp_commit();   // group 1 -> stage 1

    int s_cur = 0, s_nxt = 2;        // compute stage, prefetch stage (mod 3)

    #pragma unroll 1
    for (int kt = 0; kt < NITER; ++kt) {
        // Prefetch stage kt+2, commit as group kt+2, THEN wait so that
        // group kt (which wrote stage s_cur) is retired; <=1 group pending.
        if (kt + STAGES - 1 < NITER)
            load_stage(s_nxt, kt + STAGES - 1);
        cp_commit();
        cp_wait1();
        __syncthreads();   // all warps see stage s_cur; orders prior-iter reads
                           // before the next overwrite of this stage

        const uint32_t st  = sb + s_cur * STAGE_SMEM;
        const uint32_t sAh = st + a_off;
        const uint32_t sAl = sAh + TILE_SMEM;
        const uint32_t sBh = st + 2 * TILE_SMEM + b_off;

        if (++s_cur == STAGES) s_cur = 0;
        if (++s_nxt == STAGES) s_nxt = 0;

        #pragma unroll
        for (int h = 0; h < 2; ++h) {        // two k16 halves of BK=32
            uint32_t ah[4][4], al[4][4];
            #pragma unroll
            for (int mi = 0; mi < 4; ++mi) {
                const uint32_t ao = (uint32_t)(mi * 16 * ROW_BYTES + h * 32);
                ldsm_x4(ah[mi][0], ah[mi][1], ah[mi][2], ah[mi][3], sAh + ao);
                ldsm_x4(al[mi][0], al[mi][1], al[mi][2], al[mi][3], sAl + ao);
            }
            uint32_t bh[2][4];
            #pragma unroll
            for (int nb = 0; nb < 2; ++nb) {
                const uint32_t bo = (uint32_t)(nb * 16 * ROW_BYTES + h * 32);
                ldsm_x4(bh[nb][0], bh[nb][1], bh[nb][2], bh[nb][3], sBh + bo);
            }
            #pragma unroll
            for (int mi = 0; mi < 4; ++mi) {
                #pragma unroll
                for (int nj = 0; nj < 4; ++nj) {
                    const int nb = nj >> 1, hf = (nj & 1) * 2;
                    mma16816(acc[mi][nj], ah[mi], bh[nb][hf], bh[nb][hf + 1]);
                    mma16816(acc[mi][nj], al[mi], bh[nb][hf], bh[nb][hf + 1]);
                }
            }
        }
        __syncthreads();   // reads of stage s_cur done before group kt+1/kt+2 land here
    }

    // Epilogue: write Z tile
    const int em = bm + wm + (lane >> 2);
    const int en = bn + wn + (lane & 3) * 2;
    #pragma unroll
    for (int mi = 0; mi < 4; ++mi) {
        #pragma unroll
        for (int nj = 0; nj < 4; ++nj) {
            float* z0 = Z + (size_t)(em + mi * 16) * NDIM + en + nj * 8;
            float* z1 = z0 + (size_t)8 * NDIM;
            *reinterpret_cast<float2*>(z0) = make_float2(acc[mi][nj][0], acc[mi][nj][1]);
            *reinterpret_cast<float2*>(z1) = make_float2(acc[mi][nj][2], acc[mi][nj][3]);
        }
    }
}

// ---------------------------------------------------------------------------
// LSTM gate epilogue. Z gate order: i, f, o, g. Also writes the fp16 hi/lo
// split of h_new into the NEXT layer's A buffer (cols 0..1023).
// ---------------------------------------------------------------------------
__device__ __forceinline__ float sigmoidf_(float x) { return 1.0f / (1.0f + expf(-x)); }

__global__ __launch_bounds__(256) void lstm_epilogue_kernel(
    const float* __restrict__ c_prev, const float* __restrict__ bias,
    float* __restrict__ h_out, float* __restrict__ c_out,
    float* __restrict__ final_out,
    __half* __restrict__ nextAh, __half* __restrict__ nextAl) {
    const int idx = blockIdx.x * blockDim.x + threadIdx.x;
    const int row = idx >> 10;
    const int j   = idx & 1023;
    const size_t zb = (size_t)row * NDIM + j;

    const float zi = g_scratch[zb]           + bias[j];
    const float zf = g_scratch[zb + 1 * HID] + bias[1 * HID + j];
    const float zo = g_scratch[zb + 2 * HID] + bias[2 * HID + j];
    const float zg = g_scratch[zb + 3 * HID] + bias[3 * HID + j];

    const float ig = sigmoidf_(zi);
    const float fg = sigmoidf_(zf);
    const float og = sigmoidf_(zo);
    const float gg = tanhf(zg);

    const float c_new = c_prev[idx] * fg + gg * ig;
    const float h_new = tanhf(c_new) * og;

    h_out[idx] = h_new;
    c_out[idx] = c_new;
    if (final_out) final_out[idx] = h_new;

    if (nextAh) {
        __half hh, hl;
        split_fp16(h_new, hh, hl);
        const size_t ao = (size_t)row * KDIM + j;
        nextAh[ao] = hh;
        nextAl[ao] = hl;
    }
}

// ---------------------------------------------------------------------------
// Launch. Inputs: x, s_h, s_c, W, b. Output: [out | h_new[4] | c_new[4]].
// ---------------------------------------------------------------------------
extern "C" void kernel_launch(void* const* d_in, const int* in_sizes, int n_in,
                              void* d_out, int out_size) {
    const float* x   = (const float*)d_in[0];
    const float* s_h = (const float*)d_in[1];
    const float* s_c = (const float*)d_in[2];
    const float* W   = (const float*)d_in[3];
    const float* b   = (const float*)d_in[4];

    float* out   = (float*)d_out;
    float* hbase = out + (size_t)BATCH * HID;
    float* cbase = hbase + (size_t)4 * BATCH * HID;

    const size_t layer_state = (size_t)BATCH * HID;

    cudaFuncSetAttribute(gemm_mma_kernel,
                         cudaFuncAttributeMaxDynamicSharedMemorySize, SMEM_SZ);

    float* Zp;
    cudaGetSymbolAddress((void**)&Zp, g_scratch);
    __half* Ahp[4];
    __half* Alp[4];
    {
        __half* base_h; __half* base_l;
        cudaGetSymbolAddress((void**)&base_h, g_Ah);
        cudaGetSymbolAddress((void**)&base_l, g_Al);
        for (int l = 0; l < 4; ++l) {
            Ahp[l] = base_h + (size_t)l * BATCH * KDIM;
            Alp[l] = base_l + (size_t)l * BATCH * KDIM;
        }
    }

    // Upfront conversions: W (all layers), x -> A0, s_h -> A[l] (cols >= 1024)
    convert_W_kernel<<<dim3(NDIM / 32, KDIM / 32, 4), 256>>>(W);
    const int pgrid = (BATCH * HID / 4) / 256;   // 4096
    prep_x_kernel<<<pgrid, 256>>>(x);
    prep_sh_kernel<<<dim3(pgrid, 1, 4), 256>>>(s_h);

    dim3 ggrid(BATCH / BM, NDIM / BN);           // x-major wave shares bn (W reuse)
    const int egrid = (BATCH * HID) / 256;       // 16384

    for (int l = 0; l < 4; ++l) {
        gemm_mma_kernel<<<ggrid, 256, SMEM_SZ>>>(l, Zp);
        lstm_epilogue_kernel<<<egrid, 256>>>(
            s_c + (size_t)l * layer_state,
            b + (size_t)l * NDIM,
            hbase + (size_t)l * layer_state,
            cbase + (size_t)l * layer_state,
            (l == 3) ? out : nullptr,
            (l < 3) ? Ahp[l + 1] : nullptr,
            (l < 3) ? Alp[l + 1] : nullptr);
    }
}

// round 17
// speedup vs baseline: 3.1942x; 1.0005x over previous
#include <cuda_runtime.h>
#include <cuda_fp16.h>
#include <math.h>
#include <stdint.h>

// Problem shape (fixed): DEPTH=4, B=4096, H=E=1024, K=2048, N=4H=4096
#define BATCH 4096
#define HID   1024
#define KDIM  2048
#define NDIM  4096

// GEMM tiling
#define BM 128
#define BN 128
#define BK 32
#define STAGES 3
#define ROW_BYTES 80                       // 32 fp16 = 64B payload, padded to 80B (5x16B)
#define TILE_SMEM (128 * ROW_BYTES)        // 10240 B per operand tile
#define STAGE_SMEM (3 * TILE_SMEM)         // Ah, Al, Wh = 30720 B
#define SMEM_SZ (STAGES * STAGE_SMEM)      // 92160 B -> 2 CTAs/SM

// ---------------------------------------------------------------------------
// Device scratch (no allocations allowed)
// ---------------------------------------------------------------------------
__device__ float  g_scratch[(size_t)BATCH * NDIM];            // Z pre-activations (64 MB)
__device__ __half g_Ah[4][(size_t)BATCH * KDIM];              // per-layer [X|h] hi (64 MB)
__device__ __half g_Al[4][(size_t)BATCH * KDIM];              // per-layer [X|h] lo (64 MB)
__device__ __half g_Wh[4][(size_t)NDIM * KDIM];               // W^T fp16, [n][k]  (64 MB)

// ---------------------------------------------------------------------------
// PTX helpers (base sm_103 ISA: cp.async + ldmatrix + mma.sync)
// ---------------------------------------------------------------------------
__device__ __forceinline__ uint32_t smem_u32(const void* p) {
    uint32_t a;
    asm("{ .reg .u64 t; cvta.to.shared.u64 t, %1; cvt.u32.u64 %0, t; }"
        : "=r"(a) : "l"(p));
    return a;
}

__device__ __forceinline__ void cp_async16(uint32_t dst, const void* src) {
    asm volatile("cp.async.cg.shared.global [%0], [%1], 16;"
                 :: "r"(dst), "l"(src) : "memory");
}
__device__ __forceinline__ void cp_commit() {
    asm volatile("cp.async.commit_group;" ::: "memory");
}
__device__ __forceinline__ void cp_wait1() {
    asm volatile("cp.async.wait_group 1;" ::: "memory");
}

__device__ __forceinline__ void ldsm_x4(uint32_t& r0, uint32_t& r1,
                                        uint32_t& r2, uint32_t& r3, uint32_t addr) {
    asm volatile("ldmatrix.sync.aligned.m8n8.x4.shared.b16 {%0,%1,%2,%3}, [%4];"
                 : "=r"(r0), "=r"(r1), "=r"(r2), "=r"(r3) : "r"(addr));
}

// NOTE: no 'volatile' — register-only op; lets ptxas schedule around ldsm and
// interleave independent MMAs (the round-16 bottleneck was RAW pairs pinned
// in program order by volatile).
__device__ __forceinline__ void mma16816(float* c, const uint32_t* a,
                                         uint32_t b0, uint32_t b1) {
    asm("mma.sync.aligned.m16n8k16.row.col.f32.f16.f16.f32 "
        "{%0,%1,%2,%3}, {%4,%5,%6,%7}, {%8,%9}, {%0,%1,%2,%3};"
        : "+f"(c[0]), "+f"(c[1]), "+f"(c[2]), "+f"(c[3])
        : "r"(a[0]), "r"(a[1]), "r"(a[2]), "r"(a[3]), "r"(b0), "r"(b1));
}

// ---------------------------------------------------------------------------
// fp32 -> fp16 hi/lo split
// ---------------------------------------------------------------------------
__device__ __forceinline__ void split_fp16(float v, __half& hi, __half& lo) {
    hi = __float2half(v);
    lo = __float2half(v - __half2float(hi));
}

// W [4][2048][4096] fp32 -> Wt fp16 [4][4096][2048] (transpose, all layers)
__global__ __launch_bounds__(256) void convert_W_kernel(const float* __restrict__ W) {
    __shared__ float t[32][33];
    const int l  = blockIdx.z;
    const int nb = blockIdx.x * 32;
    const int kb = blockIdx.y * 32;
    const int tx = threadIdx.x & 31;
    const int ty = threadIdx.x >> 5;   // 0..7
    const float* Wl = W + (size_t)l * KDIM * NDIM;

    #pragma unroll
    for (int r = 0; r < 4; ++r)
        t[ty + r * 8][tx] = Wl[(size_t)(kb + ty + r * 8) * NDIM + nb + tx];
    __syncthreads();

    #pragma unroll
    for (int r = 0; r < 4; ++r) {
        const int n = nb + ty + r * 8;
        const int k = kb + tx;
        g_Wh[l][(size_t)n * KDIM + k] = __float2half(t[tx][ty + r * 8]);
    }
}

// x [4096,1024] -> A[0] cols 0..1023 (hi/lo)
__global__ __launch_bounds__(256) void prep_x_kernel(const float* __restrict__ X) {
    const int idx = blockIdx.x * 256 + threadIdx.x;   // quads over 4096x1024
    const int m = idx >> 8;                           // 256 quads per row
    const int k = (idx & 255) << 2;
    const float4 v = *reinterpret_cast<const float4*>(X + (size_t)m * HID + k);
    __half h0, l0, h1, l1, h2, l2, h3, l3;
    split_fp16(v.x, h0, l0); split_fp16(v.y, h1, l1);
    split_fp16(v.z, h2, l2); split_fp16(v.w, h3, l3);
    const size_t o = (size_t)m * KDIM + k;
    *reinterpret_cast<__half2*>(&g_Ah[0][o])     = __half2(h0, h1);
    *reinterpret_cast<__half2*>(&g_Ah[0][o + 2]) = __half2(h2, h3);
    *reinterpret_cast<__half2*>(&g_Al[0][o])     = __half2(l0, l1);
    *reinterpret_cast<__half2*>(&g_Al[0][o + 2]) = __half2(l2, l3);
}

// s_h [4][4096][1024] -> A[l] cols 1024..2047 (hi/lo), all layers
__global__ __launch_bounds__(256) void prep_sh_kernel(const float* __restrict__ SH) {
    const int l   = blockIdx.z;
    const int idx = blockIdx.x * 256 + threadIdx.x;
    const int m = idx >> 8;
    const int k = (idx & 255) << 2;
    const float4 v = *reinterpret_cast<const float4*>(
        SH + (size_t)l * BATCH * HID + (size_t)m * HID + k);
    __half h0, l0, h1, l1, h2, l2, h3, l3;
    split_fp16(v.x, h0, l0); split_fp16(v.y, h1, l1);
    split_fp16(v.z, h2, l2); split_fp16(v.w, h3, l3);
    const size_t o = (size_t)m * KDIM + HID + k;
    *reinterpret_cast<__half2*>(&g_Ah[l][o])     = __half2(h0, h1);
    *reinterpret_cast<__half2*>(&g_Ah[l][o + 2]) = __half2(h2, h3);
    *reinterpret_cast<__half2*>(&g_Al[l][o])     = __half2(l0, l1);
    *reinterpret_cast<__half2*>(&g_Al[l][o + 2]) = __half2(l2, l3);
}

// ---------------------------------------------------------------------------
// HMMA GEMM: Z[4096,4096] = A(4096x2048) @ Wt^T, fp16 2-term split.
// CTA 128x128, BK=32, 3-stage cp.async pipeline, 2 CTAs/SM, 8 warps (2m x 4n).
// Per k16 per warp: 32 x mma.sync.m16n8k16, issued as 16 hi then 16 lo so
// same-accumulator RAW pairs are ~16 issues apart (beyond HMMA latency).
// ---------------------------------------------------------------------------
__global__ __launch_bounds__(256, 2) void gemm_mma_kernel(int layer, float* __restrict__ Z) {
    extern __shared__ __align__(128) char smem[];
    const uint32_t sb = smem_u32(smem);
    const int tid  = threadIdx.x;
    const int wid  = tid >> 5;
    const int lane = tid & 31;
    const int bm = blockIdx.x * BM;
    const int bn = blockIdx.y * BN;

    const int wm = (wid & 1) * 64;
    const int wn = (wid >> 1) * 32;

    const __half* Ah_b = g_Ah[layer] + (size_t)bm * KDIM;
    const __half* Al_b = g_Al[layer] + (size_t)bm * KDIM;
    const __half* Wh_b = g_Wh[layer] + (size_t)bn * KDIM;

    // cp.async mapping: per tile, thread loads row tid>>1, chunks (tid&1)*2, +1
    const int ld_row = tid >> 1;
    const int ld_c0  = (tid & 1) * 2;

    auto load_stage = [&](int s, int kt) {
        const __half* srcs[3] = {Ah_b, Al_b, Wh_b};
        const uint32_t sbase = sb + s * STAGE_SMEM;
        const int kbase = kt * BK + ld_c0 * 8;
        #pragma unroll
        for (int t = 0; t < 3; ++t) {
            const __half* src = srcs[t] + (size_t)ld_row * KDIM + kbase;
            const uint32_t dst = sbase + t * TILE_SMEM + ld_row * ROW_BYTES + ld_c0 * 16;
            cp_async16(dst, src);
            cp_async16(dst + 16, src + 8);
        }
    };

    float acc[4][4][4];
    #pragma unroll
    for (int i = 0; i < 4; ++i)
        #pragma unroll
        for (int j = 0; j < 4; ++j)
            #pragma unroll
            for (int q = 0; q < 4; ++q) acc[i][j][q] = 0.0f;

    // ldmatrix lane addressing (80B row stride: conflict-free 8-row groups)
    const uint32_t a_off = (uint32_t)((wm + (lane & 15)) * ROW_BYTES + (lane >> 4) * 16);
    const uint32_t b_off = (uint32_t)((wn + (lane & 7) + ((lane >> 4) & 1) * 8) * ROW_BYTES
                                      + ((lane >> 3) & 1) * 16);

    const int NITER = KDIM / BK;   // 64

    load_stage(0, 0); cp_commit();   // group 0 -> stage 0
    load_stage(1, 1); cp_commit();   // group 1 -> stage 1

    int s_cur = 0, s_nxt = 2;        // compute stage, prefetch stage (mod 3)

    #pragma unroll 1
    for (int kt = 0; kt < NITER; ++kt) {
        // Prefetch stage kt+2, commit as group kt+2, THEN wait so the group
        // that wrote stage s_cur is provably retired; <=1 group pending.
        if (kt + STAGES - 1 < NITER)
            load_stage(s_nxt, kt + STAGES - 1);
        cp_commit();
        cp_wait1();
        __syncthreads();

        const uint32_t st  = sb + s_cur * STAGE_SMEM;
        const uint32_t sAh = st + a_off;
        const uint32_t sAl = sAh + TILE_SMEM;
        const uint32_t sBh = st + 2 * TILE_SMEM + b_off;

        if (++s_cur == STAGES) s_cur = 0;
        if (++s_nxt == STAGES) s_nxt = 0;

        #pragma unroll
        for (int h = 0; h < 2; ++h) {        // two k16 halves of BK=32
            uint32_t ah[4][4], al[4][4];
            #pragma unroll
            for (int mi = 0; mi < 4; ++mi) {
                const uint32_t ao = (uint32_t)(mi * 16 * ROW_BYTES + h * 32);
                ldsm_x4(ah[mi][0], ah[mi][1], ah[mi][2], ah[mi][3], sAh + ao);
                ldsm_x4(al[mi][0], al[mi][1], al[mi][2], al[mi][3], sAl + ao);
            }
            uint32_t bh[2][4];
            #pragma unroll
            for (int nb = 0; nb < 2; ++nb) {
                const uint32_t bo = (uint32_t)(nb * 16 * ROW_BYTES + h * 32);
                ldsm_x4(bh[nb][0], bh[nb][1], bh[nb][2], bh[nb][3], sBh + bo);
            }
            // Stream 1: all hi-term MMAs (16, independent accumulators)
            #pragma unroll
            for (int mi = 0; mi < 4; ++mi) {
                #pragma unroll
                for (int nj = 0; nj < 4; ++nj) {
                    const int nb = nj >> 1, hf = (nj & 1) * 2;
                    mma16816(acc[mi][nj], ah[mi], bh[nb][hf], bh[nb][hf + 1]);
                }
            }
            // Stream 2: all lo-term MMAs (same accs, now 16 issues later)
            #pragma unroll
            for (int mi = 0; mi < 4; ++mi) {
                #pragma unroll
                for (int nj = 0; nj < 4; ++nj) {
                    const int nb = nj >> 1, hf = (nj & 1) * 2;
                    mma16816(acc[mi][nj], al[mi], bh[nb][hf], bh[nb][hf + 1]);
                }
            }
        }
        __syncthreads();   // reads of stage s_cur done before it is overwritten
    }

    // Epilogue: write Z tile
    const int em = bm + wm + (lane >> 2);
    const int en = bn + wn + (lane & 3) * 2;
    #pragma unroll
    for (int mi = 0; mi < 4; ++mi) {
        #pragma unroll
        for (int nj = 0; nj < 4; ++nj) {
            float* z0 = Z + (size_t)(em + mi * 16) * NDIM + en + nj * 8;
            float* z1 = z0 + (size_t)8 * NDIM;
            *reinterpret_cast<float2*>(z0) = make_float2(acc[mi][nj][0], acc[mi][nj][1]);
            *reinterpret_cast<float2*>(z1) = make_float2(acc[mi][nj][2], acc[mi][nj][3]);
        }
    }
}

// ---------------------------------------------------------------------------
// LSTM gate epilogue. Z gate order: i, f, o, g. Also writes the fp16 hi/lo
// split of h_new into the NEXT layer's A buffer (cols 0..1023).
// ---------------------------------------------------------------------------
__device__ __forceinline__ float sigmoidf_(float x) { return 1.0f / (1.0f + expf(-x)); }

__global__ __launch_bounds__(256) void lstm_epilogue_kernel(
    const float* __restrict__ c_prev, const float* __restrict__ bias,
    float* __restrict__ h_out, float* __restrict__ c_out,
    float* __restrict__ final_out,
    __half* __restrict__ nextAh, __half* __restrict__ nextAl) {
    const int idx = blockIdx.x * blockDim.x + threadIdx.x;
    const int row = idx >> 10;
    const int j   = idx & 1023;
    const size_t zb = (size_t)row * NDIM + j;

    const float zi = g_scratch[zb]           + bias[j];
    const float zf = g_scratch[zb + 1 * HID] + bias[1 * HID + j];
    const float zo = g_scratch[zb + 2 * HID] + bias[2 * HID + j];
    const float zg = g_scratch[zb + 3 * HID] + bias[3 * HID + j];

    const float ig = sigmoidf_(zi);
    const float fg = sigmoidf_(zf);
    const float og = sigmoidf_(zo);
    const float gg = tanhf(zg);

    const float c_new = c_prev[idx] * fg + gg * ig;
    const float h_new = tanhf(c_new) * og;

    h_out[idx] = h_new;
    c_out[idx] = c_new;
    if (final_out) final_out[idx] = h_new;

    if (nextAh) {
        __half hh, hl;
        split_fp16(h_new, hh, hl);
        const size_t ao = (size_t)row * KDIM + j;
        nextAh[ao] = hh;
        nextAl[ao] = hl;
    }
}

// ---------------------------------------------------------------------------
// Launch. Inputs: x, s_h, s_c, W, b. Output: [out | h_new[4] | c_new[4]].
// ---------------------------------------------------------------------------
extern "C" void kernel_launch(void* const* d_in, const int* in_sizes, int n_in,
                              void* d_out, int out_size) {
    const float* x   = (const float*)d_in[0];
    const float* s_h = (const float*)d_in[1];
    const float* s_c = (const float*)d_in[2];
    const float* W   = (const float*)d_in[3];
    const float* b   = (const float*)d_in[4];

    float* out   = (float*)d_out;
    float* hbase = out + (size_t)BATCH * HID;
    float* cbase = hbase + (size_t)4 * BATCH * HID;

    const size_t layer_state = (size_t)BATCH * HID;

    cudaFuncSetAttribute(gemm_mma_kernel,
                         cudaFuncAttributeMaxDynamicSharedMemorySize, SMEM_SZ);

    float* Zp;
    cudaGetSymbolAddress((void**)&Zp, g_scratch);
    __half* Ahp[4];
    __half* Alp[4];
    {
        __half* base_h; __half* base_l;
        cudaGetSymbolAddress((void**)&base_h, g_Ah);
        cudaGetSymbolAddress((void**)&base_l, g_Al);
        for (int l = 0; l < 4; ++l) {
            Ahp[l] = base_h + (size_t)l * BATCH * KDIM;
            Alp[l] = base_l + (size_t)l * BATCH * KDIM;
        }
    }

    // Upfront conversions: W (all layers), x -> A0, s_h -> A[l] (cols >= 1024)
    convert_W_kernel<<<dim3(NDIM / 32, KDIM / 32, 4), 256>>>(W);
    const int pgrid = (BATCH * HID / 4) / 256;   // 4096
    prep_x_kernel<<<pgrid, 256>>>(x);
    prep_sh_kernel<<<dim3(pgrid, 1, 4), 256>>>(s_h);

    dim3 ggrid(BATCH / BM, NDIM / BN);           // x-major wave shares bn (W reuse)
    const int egrid = (BATCH * HID) / 256;       // 16384

    for (int l = 0; l < 4; ++l) {
        gemm_mma_kernel<<<ggrid, 256, SMEM_SZ>>>(l, Zp);
        lstm_epilogue_kernel<<<egrid, 256>>>(
            s_c + (size_t)l * layer_state,
            b + (size_t)l * NDIM,
            hbase + (size_t)l * layer_state,
            cbase + (size_t)l * layer_state,
            (l == 3) ? out : nullptr,
            (l < 3) ? Ahp[l + 1] : nullptr,
            (l < 3) ? Alp[l + 1] : nullptr);
    }
}